// round 3
// baseline (speedup 1.0000x reference)
#include <cuda_runtime.h>
#include <cuda_bf16.h>
#include <math_constants.h>

#define MAXN 100000
#define MAXE 1600000
#define IN_DIM 128
#define EDGE_DIM 16
#define NH 4
#define OUT_H 64
#define F_MLP 272   // 2*128+16

// ---------------- device scratch ----------------------------------------------
__device__ int   g_rowptr[MAXN + 1];
__device__ float g_attn12[(size_t)MAXN * 8];           // [n][0:4]=attn1,[4:8]=attn2
__device__ float g_lg[(size_t)MAXE * 4];               // edge logits (big-degree path)
__device__ float g_xobj[(size_t)MAXN * NH * IN_DIM];   // [n][h][128]
__device__ float g_xe[(size_t)MAXN * NH * EDGE_DIM];   // [n][h][16]
__device__ float g_h1[(size_t)MAXN * NH * OUT_H];      // [n][h][64]
__device__ float g_sum[NH * OUT_H];
__device__ float g_sqsum[NH * OUT_H];
__device__ float g_a[NH * OUT_H];
__device__ float g_c[NH * OUT_H];
__device__ float g_w1p[NH * F_MLP * OUT_H];            // [h][fp][o][2] interleaved f-pairs
__device__ float g_w2p[NH * OUT_H * OUT_H];            // [h][op][p][2]

// ---------------- f32x2 helpers -----------------------------------------------
__device__ __forceinline__ void ffma2(unsigned long long& d, unsigned long long a,
                                      unsigned long long b) {
    asm("fma.rn.f32x2 %0, %1, %2, %0;" : "+l"(d) : "l"(a), "l"(b));
}
__device__ __forceinline__ void unpack2(unsigned long long v, float& lo, float& hi) {
    asm("mov.b64 {%0,%1}, %2;" : "=f"(lo), "=f"(hi) : "l"(v));
}

// ---------------- K0: CSR row pointers ----------------------------------------
__global__ void k_rowptr(const int* __restrict__ row, int n, int e) {
    int i = blockIdx.x * blockDim.x + threadIdx.x;
    if (i > n) return;
    int lo = 0, hi = e;
    while (lo < hi) { int mid = (lo + hi) >> 1; if (row[mid] < i) lo = mid + 1; else hi = mid; }
    g_rowptr[i] = lo;
}

// ---------------- K1: per-node attention logits -------------------------------
__global__ void k_nodelogits(const float* __restrict__ x, const float* __restrict__ a1w,
                             const float* __restrict__ a2w, int n) {
    __shared__ float sw[8 * 128];
    int tid = threadIdx.x;
    for (int i = tid; i < 512; i += 256) { sw[i] = a1w[i]; sw[512 + i] = a2w[i]; }
    __syncthreads();
    int warp = tid >> 5, lane = tid & 31;
    int nd = blockIdx.x * 8 + warp;
    if (nd >= n) return;
    float4 xv = *(const float4*)(x + (size_t)nd * 128 + lane * 4);
#pragma unroll
    for (int k = 0; k < 8; k++) {
        float4 wv = *(const float4*)(sw + k * 128 + lane * 4);
        float p = xv.x * wv.x + xv.y * wv.y + xv.z * wv.z + xv.w * wv.w;
        p += __shfl_xor_sync(0xffffffffu, p, 16);
        p += __shfl_xor_sync(0xffffffffu, p, 8);
        p += __shfl_xor_sync(0xffffffffu, p, 4);
        p += __shfl_xor_sync(0xffffffffu, p, 2);
        p += __shfl_xor_sync(0xffffffffu, p, 1);
        if (lane == 0) g_attn12[(size_t)nd * 8 + k] = p;
    }
}

// ---------------- K_pre: interleave weights as f-pairs + zero stats -----------
__global__ void k_pre(const float* __restrict__ w1, const float* __restrict__ w2) {
    int h = blockIdx.x, tid = threadIdx.x;
    // g_w1p[h][fp*128 + o*2 + r] = w1[h][o][2fp+r]
    for (int i = tid; i < F_MLP * OUT_H; i += blockDim.x) {
        int fp = i >> 7, rem = i & 127, o = rem >> 1, r = rem & 1;
        g_w1p[(size_t)h * (F_MLP * OUT_H) + i] =
            w1[(size_t)h * (F_MLP * OUT_H) + o * F_MLP + 2 * fp + r];
    }
    // g_w2p[h][op*128 + p*2 + r] = w2[h][p][2op+r]
    for (int i = tid; i < OUT_H * OUT_H; i += blockDim.x) {
        int op = i >> 7, rem = i & 127, p = rem >> 1, r = rem & 1;
        g_w2p[h * 4096 + i] = w2[h * 4096 + p * 64 + 2 * op + r];
    }
    if (h == 0) { g_sum[tid] = 0.f; g_sqsum[tid] = 0.f; }   // blockDim == 256
}

// ---------------- K2: edge softmax + aggregation (warp per node) --------------
__device__ __forceinline__ void edge_logits(const float* __restrict__ ea,
                                            const float* s_aew, int e2, int ci,
                                            const float* a1h, float* lg) {
    const float4* ep = (const float4*)(ea + (size_t)e2 * 16);
    float4 q0 = ep[0], q1 = ep[1], q2 = ep[2], q3 = ep[3];
    float4 a2v = *(const float4*)(g_attn12 + (size_t)ci * 8 + 4);
    float a2a[4] = {a2v.x, a2v.y, a2v.z, a2v.w};
#pragma unroll
    for (int h = 0; h < 4; h++) {
        const float* wq = s_aew + h * 16;
        float d = q0.x * wq[0] + q0.y * wq[1] + q0.z * wq[2] + q0.w * wq[3]
                + q1.x * wq[4] + q1.y * wq[5] + q1.z * wq[6] + q1.w * wq[7]
                + q2.x * wq[8] + q2.y * wq[9] + q2.z * wq[10] + q2.w * wq[11]
                + q3.x * wq[12] + q3.y * wq[13] + q3.z * wq[14] + q3.w * wq[15];
        lg[h] = (a1h[h] + a2a[h] + d) * 0.125f;
    }
}

__global__ void __launch_bounds__(256) k_edge(const float* __restrict__ x,
                                              const int* __restrict__ col,
                                              const float* __restrict__ ea,
                                              const float* __restrict__ aew, int n) {
    __shared__ float s_aew[64];
    __shared__ float s_w[8 * 32 * 4];   // per warp: [j][h]
    __shared__ int   s_c[8 * 32];
    int tid = threadIdx.x;
    if (tid < 64) s_aew[tid] = aew[tid];
    __syncthreads();
    int warp = tid >> 5, lane = tid & 31;
    int nd = blockIdx.x * 8 + warp;
    if (nd >= n) return;
    int start = g_rowptr[nd], end = g_rowptr[nd + 1];
    int deg = end - start;
    float a1h[4];
    {
        float4 a1v = *(const float4*)(g_attn12 + (size_t)nd * 8);
        a1h[0] = a1v.x; a1h[1] = a1v.y; a1h[2] = a1v.z; a1h[3] = a1v.w;
    }
    float* swp = s_w + warp * 128;
    int*   scp = s_c + warp * 32;

    float m[4], inv[4];

    if (deg <= 32) {
        // ---- fast path: single chunk, direct softmax, no scratch ----
        int e2 = start + lane;
        bool have = (e2 < end);
        float lg[4] = {-CUDART_INF_F, -CUDART_INF_F, -CUDART_INF_F, -CUDART_INF_F};
        int ci = 0;
        if (have) { ci = col[e2]; edge_logits(ea, s_aew, e2, ci, a1h, lg); }
#pragma unroll
        for (int h = 0; h < 4; h++) {
            float mm = lg[h];
#pragma unroll
            for (int off = 16; off >= 1; off >>= 1)
                mm = fmaxf(mm, __shfl_xor_sync(0xffffffffu, mm, off));
            float ex = have ? __expf(lg[h] - mm) : 0.f;
            float ssum = ex;
#pragma unroll
            for (int off = 16; off >= 1; off >>= 1)
                ssum += __shfl_xor_sync(0xffffffffu, ssum, off);
            float iv = 1.f / (ssum + 1e-16f);
            swp[lane * 4 + h] = ex * iv;
        }
        scp[lane] = ci;
        m[0] = 0.f; // unused
    } else {
        // ---- general path: online softmax, logits to gmem scratch ----
        float mm[4] = {-CUDART_INF_F, -CUDART_INF_F, -CUDART_INF_F, -CUDART_INF_F};
        float s[4] = {0.f, 0.f, 0.f, 0.f};
        for (int base = start; base < end; base += 32) {
            int e2 = base + lane;
            if (e2 < end) {
                int ci = col[e2];
                float lg[4];
                edge_logits(ea, s_aew, e2, ci, a1h, lg);
                *(float4*)(g_lg + (size_t)e2 * 4) = make_float4(lg[0], lg[1], lg[2], lg[3]);
#pragma unroll
                for (int h = 0; h < 4; h++) {
                    if (lg[h] > mm[h]) { s[h] = s[h] * __expf(mm[h] - lg[h]) + 1.f; mm[h] = lg[h]; }
                    else               { s[h] += __expf(lg[h] - mm[h]); }
                }
            }
        }
#pragma unroll
        for (int off = 16; off >= 1; off >>= 1) {
#pragma unroll
            for (int h = 0; h < 4; h++) {
                float om = __shfl_xor_sync(0xffffffffu, mm[h], off);
                float os = __shfl_xor_sync(0xffffffffu, s[h], off);
                float nm = fmaxf(mm[h], om);
                float t = (s[h] > 0.f ? s[h] * __expf(mm[h] - nm) : 0.f)
                        + (os > 0.f ? os * __expf(om - nm) : 0.f);
                mm[h] = nm; s[h] = t;
            }
        }
#pragma unroll
        for (int h = 0; h < 4; h++) { m[h] = mm[h]; inv[h] = 1.f / (s[h] + 1e-16f); }
    }

    // ---- aggregation ----
    float4 acc[4];
#pragma unroll
    for (int h = 0; h < 4; h++) acc[h] = make_float4(0.f, 0.f, 0.f, 0.f);
    float acce[4] = {0.f, 0.f, 0.f, 0.f};

    for (int base = start; base < end; base += 32) {
        int cnt = min(32, end - base);
        if (deg > 32) {
            int e2 = base + lane;
            __syncwarp();
            if (e2 < end) {
                float4 lgv = *(const float4*)(g_lg + (size_t)e2 * 4);
                swp[lane * 4 + 0] = __expf(lgv.x - m[0]) * inv[0];
                swp[lane * 4 + 1] = __expf(lgv.y - m[1]) * inv[1];
                swp[lane * 4 + 2] = __expf(lgv.z - m[2]) * inv[2];
                swp[lane * 4 + 3] = __expf(lgv.w - m[3]) * inv[3];
                scp[lane] = col[e2];
            }
        }
        __syncwarp();
#pragma unroll 4
        for (int j = 0; j < cnt; j++) {
            int cj = scp[j];
            float4 wv = *(const float4*)(swp + j * 4);
            float4 xv = *(const float4*)(x + (size_t)cj * 128 + lane * 4);
            acc[0].x += wv.x * xv.x; acc[0].y += wv.x * xv.y; acc[0].z += wv.x * xv.z; acc[0].w += wv.x * xv.w;
            acc[1].x += wv.y * xv.x; acc[1].y += wv.y * xv.y; acc[1].z += wv.y * xv.z; acc[1].w += wv.y * xv.w;
            acc[2].x += wv.z * xv.x; acc[2].y += wv.z * xv.y; acc[2].z += wv.z * xv.z; acc[2].w += wv.z * xv.w;
            acc[3].x += wv.w * xv.x; acc[3].y += wv.w * xv.y; acc[3].z += wv.w * xv.z; acc[3].w += wv.w * xv.w;
            if (lane < 16) {
                float eav = ea[(size_t)(base + j) * 16 + lane];
                acce[0] += wv.x * eav; acce[1] += wv.y * eav;
                acce[2] += wv.z * eav; acce[3] += wv.w * eav;
            }
        }
    }
    size_t ob = (size_t)nd * (NH * IN_DIM);
#pragma unroll
    for (int h = 0; h < 4; h++)
        *(float4*)(g_xobj + ob + h * 128 + lane * 4) = acc[h];
    if (lane < 16) {
#pragma unroll
        for (int h = 0; h < 4; h++)
            g_xe[(size_t)nd * 64 + h * 16 + lane] = acce[h];
    }
}

// ---------------- K3: MLP layer 1 + ReLU + BN stats ---------------------------
// 512 thr, tile 128 nodes x 64 outs; f32x2 pairs over f-parity.
#define SF_STRIDE 274
#define K3_SMEM ((F_MLP * OUT_H + 128 * SF_STRIDE + 2048) * 4)
__global__ void __launch_bounds__(512) k_mlp1(const float* __restrict__ x,
                                              const float* __restrict__ b1, int n) {
    extern __shared__ float smem[];
    float* sW = smem;                        // [136 fp][64 o][2]
    float* sF = smem + F_MLP * OUT_H;        // [128 node][274]
    float* sRed = sF + 128 * SF_STRIDE;
    int h = blockIdx.y;
    int n0 = blockIdx.x * 128;
    int tid = threadIdx.x;

    const float* w1p = g_w1p + (size_t)h * (F_MLP * OUT_H);
    for (int i = tid; i < F_MLP * OUT_H; i += 512) sW[i] = w1p[i];
    for (int i = tid; i < 128 * F_MLP; i += 512) {
        int nl = i / F_MLP, f = i - nl * F_MLP;
        int nd = n0 + nl;
        float v = 0.f;
        if (nd < n) {
            if (f < 128)      v = x[(size_t)nd * 128 + f];
            else if (f < 256) v = g_xobj[(size_t)nd * 512 + h * 128 + (f - 128)];
            else              v = g_xe[(size_t)nd * 64 + h * 16 + (f - 256)];
        }
        sF[nl * SF_STRIDE + f] = v;
    }
    __syncthreads();

    int to = tid & 15, tn = tid >> 4;        // 4 outs x 4 nodes per thread
    unsigned long long acc[4][4];
#pragma unroll
    for (int i = 0; i < 4; i++)
#pragma unroll
        for (int o = 0; o < 4; o++) acc[i][o] = 0ull;
    const float* fb = sF + tn * 4 * SF_STRIDE;
    const float* wb = sW + to * 8;
#pragma unroll 2
    for (int fp = 0; fp < F_MLP / 2; fp++) {
        ulonglong2 wA = *(const ulonglong2*)(wb + fp * 128);
        ulonglong2 wB = *(const ulonglong2*)(wb + fp * 128 + 4);
#pragma unroll
        for (int i = 0; i < 4; i++) {
            unsigned long long fv = *(const unsigned long long*)(fb + i * SF_STRIDE + 2 * fp);
            ffma2(acc[i][0], fv, wA.x);
            ffma2(acc[i][1], fv, wA.y);
            ffma2(acc[i][2], fv, wB.x);
            ffma2(acc[i][3], fv, wB.y);
        }
    }
    float4 b1q = *(const float4*)(b1 + h * 64 + to * 4);
    float ps[4] = {0.f, 0.f, 0.f, 0.f}, pq[4] = {0.f, 0.f, 0.f, 0.f};
#pragma unroll
    for (int i = 0; i < 4; i++) {
        float v[4];
#pragma unroll
        for (int o = 0; o < 4; o++) {
            float lo, hi; unpack2(acc[i][o], lo, hi);
            v[o] = lo + hi;
        }
        v[0] = fmaxf(v[0] + b1q.x, 0.f); v[1] = fmaxf(v[1] + b1q.y, 0.f);
        v[2] = fmaxf(v[2] + b1q.z, 0.f); v[3] = fmaxf(v[3] + b1q.w, 0.f);
        int nd = n0 + tn * 4 + i;
        if (nd < n) {
            *(float4*)(g_h1 + ((size_t)nd * 4 + h) * 64 + to * 4) = make_float4(v[0], v[1], v[2], v[3]);
#pragma unroll
            for (int o = 0; o < 4; o++) { ps[o] += v[o]; pq[o] += v[o] * v[o]; }
        }
    }
#pragma unroll
    for (int j = 0; j < 4; j++) {
        ps[j] += __shfl_xor_sync(0xffffffffu, ps[j], 16);
        pq[j] += __shfl_xor_sync(0xffffffffu, pq[j], 16);
    }
    int warp = tid >> 5;
    if ((tid & 31) < 16) {
#pragma unroll
        for (int j = 0; j < 4; j++) {
            sRed[warp * 64 + to * 4 + j] = ps[j];
            sRed[1024 + warp * 64 + to * 4 + j] = pq[j];
        }
    }
    __syncthreads();
    if (tid < 64) {
        float s1 = 0.f, s2 = 0.f;
        for (int w2i = 0; w2i < 16; w2i++) {
            s1 += sRed[w2i * 64 + tid];
            s2 += sRed[1024 + w2i * 64 + tid];
        }
        atomicAdd(&g_sum[h * 64 + tid], s1);
        atomicAdd(&g_sqsum[h * 64 + tid], s2);
    }
}

// ---------------- K4: finalize BN stats ---------------------------------------
__global__ void k_stats(const float* __restrict__ gamma, const float* __restrict__ beta, int n) {
    int i = threadIdx.x;   // 256
    float inv_n = 1.f / (float)n;
    float mu = g_sum[i] * inv_n;
    float var = g_sqsum[i] * inv_n - mu * mu;
    float r = rsqrtf(var + 1e-5f);
    float a = r * gamma[i];
    g_a[i] = a;
    g_c[i] = beta[i] - mu * a;
}

// ---------------- K5: BN apply + MLP layer 2 ----------------------------------
#define SH_STRIDE 66
#define K5_SMEM ((4096 + 128 * SH_STRIDE + 128) * 4)
__global__ void __launch_bounds__(512) k_mlp2(const float* __restrict__ b2,
                                              float* __restrict__ out, int n) {
    extern __shared__ float smem[];
    float* sW = smem;              // [32 op][64 p][2]
    float* sH = smem + 4096;       // [128 node][66]
    float* sAC = sH + 128 * SH_STRIDE;  // a[64], c[64]
    int h = blockIdx.y;
    int n0 = blockIdx.x * 128;
    int tid = threadIdx.x;
    if (tid < 64)       sAC[tid] = g_a[h * 64 + tid];
    else if (tid < 128) sAC[tid] = g_c[h * 64 + tid - 64];
    for (int i = tid; i < 4096; i += 512) sW[i] = g_w2p[h * 4096 + i];
    __syncthreads();
    for (int i = tid; i < 128 * 64; i += 512) {
        int nl = i >> 6, o = i & 63;
        int nd = n0 + nl;
        float v = 0.f;
        if (nd < n) v = g_h1[((size_t)nd * 4 + h) * 64 + o] * sAC[o] + sAC[64 + o];
        sH[nl * SH_STRIDE + o] = v;
    }
    __syncthreads();
    int to = tid & 15, tn = tid >> 4;
    unsigned long long acc[4][4];
#pragma unroll
    for (int i = 0; i < 4; i++)
#pragma unroll
        for (int o = 0; o < 4; o++) acc[i][o] = 0ull;
    const float* hb = sH + tn * 4 * SH_STRIDE;
    const float* wb = sW + to * 8;
#pragma unroll 4
    for (int op = 0; op < 32; op++) {
        ulonglong2 wA = *(const ulonglong2*)(wb + op * 128);
        ulonglong2 wB = *(const ulonglong2*)(wb + op * 128 + 4);
#pragma unroll
        for (int i = 0; i < 4; i++) {
            unsigned long long fv = *(const unsigned long long*)(hb + i * SH_STRIDE + 2 * op);
            ffma2(acc[i][0], fv, wA.x);
            ffma2(acc[i][1], fv, wA.y);
            ffma2(acc[i][2], fv, wB.x);
            ffma2(acc[i][3], fv, wB.y);
        }
    }
    float4 b2q = *(const float4*)(b2 + h * 64 + to * 4);
#pragma unroll
    for (int i = 0; i < 4; i++) {
        int nd = n0 + tn * 4 + i;
        if (nd < n) {
            float v[4];
#pragma unroll
            for (int o = 0; o < 4; o++) {
                float lo, hi; unpack2(acc[i][o], lo, hi);
                v[o] = lo + hi;
            }
            *(float4*)(out + (size_t)nd * 256 + h * 64 + to * 4) =
                make_float4(v[0] + b2q.x, v[1] + b2q.y, v[2] + b2q.z, v[3] + b2q.w);
        }
    }
}

// ---------------- launch ------------------------------------------------------
extern "C" void kernel_launch(void* const* d_in, const int* in_sizes, int n_in,
                              void* d_out, int out_size) {
    const float* x     = (const float*)d_in[0];
    const int*   row   = (const int*)d_in[1];
    const int*   col   = (const int*)d_in[2];
    const float* ea    = (const float*)d_in[3];
    const float* a1w   = (const float*)d_in[4];
    const float* a2w   = (const float*)d_in[5];
    const float* aew   = (const float*)d_in[6];
    const float* w1    = (const float*)d_in[7];
    const float* b1    = (const float*)d_in[8];
    const float* gamma = (const float*)d_in[9];
    const float* beta  = (const float*)d_in[10];
    const float* w2    = (const float*)d_in[11];
    const float* b2    = (const float*)d_in[12];
    float* out = (float*)d_out;

    int n = in_sizes[0] / IN_DIM;
    int e = in_sizes[1];

    cudaFuncSetAttribute(k_mlp1, cudaFuncAttributeMaxDynamicSharedMemorySize, K3_SMEM);
    cudaFuncSetAttribute(k_mlp2, cudaFuncAttributeMaxDynamicSharedMemorySize, K5_SMEM);

    k_rowptr<<<(n + 256) / 256, 256>>>(row, n, e);
    k_nodelogits<<<(n + 7) / 8, 256>>>(x, a1w, a2w, n);
    k_pre<<<4, 256>>>(w1, w2);
    k_edge<<<(n + 7) / 8, 256>>>(x, col, ea, aew, n);
    dim3 g3((n + 127) / 128, 4);
    k_mlp1<<<g3, 512, K3_SMEM>>>(x, b1, n);
    k_stats<<<1, 256>>>(gamma, beta, n);
    k_mlp2<<<g3, 512, K5_SMEM>>>(b2, out, n);
}

// round 5
// speedup vs baseline: 1.2515x; 1.2515x over previous
#include <cuda_runtime.h>
#include <cuda_bf16.h>
#include <math_constants.h>

#define MAXN 100000
#define MAXE 1600000
#define IN_DIM 128
#define EDGE_DIM 16
#define NH 4
#define OUT_H 64
#define F_MLP 272   // 2*128+16

// ---------------- device scratch ----------------------------------------------
__device__ int   g_rowptr[MAXN + 1];
__device__ float g_attn12[(size_t)MAXN * 8];           // [n][0:4]=attn1,[4:8]=attn2
__device__ float g_lg[(size_t)MAXE * 4];               // edge logits (big-degree path)
__device__ float g_xobj[(size_t)MAXN * NH * IN_DIM];   // [n][h][128]
__device__ float g_xe[(size_t)MAXN * NH * EDGE_DIM];   // [n][h][16]
__device__ float g_h1[(size_t)MAXN * NH * OUT_H];      // [n][h][64]
__device__ float g_sum[NH * OUT_H];
__device__ float g_sqsum[NH * OUT_H];
__device__ float g_a[NH * OUT_H];
__device__ float g_c[NH * OUT_H];
// lane-contiguous f32x2 weight layout:
// g_w1p[h][fp][half][to][q][r] ; o = 4*to + 2*half + q ; f = 2*fp + r
__device__ float g_w1p[NH * F_MLP * OUT_H];
__device__ float g_w2p[NH * OUT_H * OUT_H];

// ---------------- f32x2 helpers -----------------------------------------------
__device__ __forceinline__ void ffma2(unsigned long long& d, unsigned long long a,
                                      unsigned long long b) {
    asm("fma.rn.f32x2 %0, %1, %2, %0;" : "+l"(d) : "l"(a), "l"(b));
}
__device__ __forceinline__ void unpack2(unsigned long long v, float& lo, float& hi) {
    asm("mov.b64 {%0,%1}, %2;" : "=f"(lo), "=f"(hi) : "l"(v));
}

// ---------------- K0: CSR row pointers ----------------------------------------
__global__ void k_rowptr(const int* __restrict__ row, int n, int e) {
    int i = blockIdx.x * blockDim.x + threadIdx.x;
    if (i > n) return;
    int lo = 0, hi = e;
    while (lo < hi) { int mid = (lo + hi) >> 1; if (row[mid] < i) lo = mid + 1; else hi = mid; }
    g_rowptr[i] = lo;
}

// ---------------- K1: per-node attention logits -------------------------------
__global__ void k_nodelogits(const float* __restrict__ x, const float* __restrict__ a1w,
                             const float* __restrict__ a2w, int n) {
    __shared__ float sw[8 * 128];
    int tid = threadIdx.x;
    for (int i = tid; i < 512; i += 256) { sw[i] = a1w[i]; sw[512 + i] = a2w[i]; }
    __syncthreads();
    int warp = tid >> 5, lane = tid & 31;
    int nd = blockIdx.x * 8 + warp;
    if (nd >= n) return;
    float4 xv = *(const float4*)(x + (size_t)nd * 128 + lane * 4);
#pragma unroll
    for (int k = 0; k < 8; k++) {
        float4 wv = *(const float4*)(sw + k * 128 + lane * 4);
        float p = xv.x * wv.x + xv.y * wv.y + xv.z * wv.z + xv.w * wv.w;
        p += __shfl_xor_sync(0xffffffffu, p, 16);
        p += __shfl_xor_sync(0xffffffffu, p, 8);
        p += __shfl_xor_sync(0xffffffffu, p, 4);
        p += __shfl_xor_sync(0xffffffffu, p, 2);
        p += __shfl_xor_sync(0xffffffffu, p, 1);
        if (lane == 0) g_attn12[(size_t)nd * 8 + k] = p;
    }
}

// ---------------- K_pre: permute weights to lane-contiguous f-pair layout -----
__global__ void k_pre(const float* __restrict__ w1, const float* __restrict__ w2) {
    int h = blockIdx.x, tid = threadIdx.x;
    for (int i = tid; i < F_MLP * OUT_H; i += blockDim.x) {
        int fp = i >> 7, rem = i & 127;
        int half = (rem >> 6) & 1, to = (rem >> 2) & 15, q = (rem >> 1) & 1, r = rem & 1;
        int o = to * 4 + half * 2 + q;
        int f = 2 * fp + r;
        g_w1p[(size_t)h * (F_MLP * OUT_H) + i] =
            w1[(size_t)h * (F_MLP * OUT_H) + o * F_MLP + f];
    }
    for (int i = tid; i < OUT_H * OUT_H; i += blockDim.x) {
        int op = i >> 7, rem = i & 127;
        int half = (rem >> 6) & 1, to = (rem >> 2) & 15, q = (rem >> 1) & 1, r = rem & 1;
        int p = to * 4 + half * 2 + q;
        int o = 2 * op + r;
        g_w2p[h * 4096 + i] = w2[h * 4096 + p * 64 + o];
    }
    if (h == 0) { g_sum[tid] = 0.f; g_sqsum[tid] = 0.f; }   // blockDim == 256
}

// ---------------- K2: edge softmax + aggregation (warp per node) --------------
__device__ __forceinline__ void edge_logits(const float* __restrict__ ea,
                                            const float* s_aew, int e2, int ci,
                                            const float* a1h, float* lg) {
    const float4* ep = (const float4*)(ea + (size_t)e2 * 16);
    float4 q0 = ep[0], q1 = ep[1], q2 = ep[2], q3 = ep[3];
    float4 a2v = *(const float4*)(g_attn12 + (size_t)ci * 8 + 4);
    float a2a[4] = {a2v.x, a2v.y, a2v.z, a2v.w};
#pragma unroll
    for (int h = 0; h < 4; h++) {
        const float* wq = s_aew + h * 16;
        float d = q0.x * wq[0] + q0.y * wq[1] + q0.z * wq[2] + q0.w * wq[3]
                + q1.x * wq[4] + q1.y * wq[5] + q1.z * wq[6] + q1.w * wq[7]
                + q2.x * wq[8] + q2.y * wq[9] + q2.z * wq[10] + q2.w * wq[11]
                + q3.x * wq[12] + q3.y * wq[13] + q3.z * wq[14] + q3.w * wq[15];
        lg[h] = (a1h[h] + a2a[h] + d) * 0.125f;
    }
}

__global__ void __launch_bounds__(256) k_edge(const float* __restrict__ x,
                                              const int* __restrict__ col,
                                              const float* __restrict__ ea,
                                              const float* __restrict__ aew, int n) {
    __shared__ float s_aew[64];
    __shared__ float s_w[8 * 32 * 4];   // per warp: [j][h]
    __shared__ int   s_c[8 * 32];
    int tid = threadIdx.x;
    if (tid < 64) s_aew[tid] = aew[tid];
    __syncthreads();
    int warp = tid >> 5, lane = tid & 31;
    int nd = blockIdx.x * 8 + warp;
    if (nd >= n) return;
    int start = g_rowptr[nd], end = g_rowptr[nd + 1];
    int deg = end - start;
    float a1h[4];
    {
        float4 a1v = *(const float4*)(g_attn12 + (size_t)nd * 8);
        a1h[0] = a1v.x; a1h[1] = a1v.y; a1h[2] = a1v.z; a1h[3] = a1v.w;
    }
    float* swp = s_w + warp * 128;
    int*   scp = s_c + warp * 32;

    float m[4], inv[4];

    if (deg <= 32) {
        int e2 = start + lane;
        bool have = (e2 < end);
        float lg[4] = {-CUDART_INF_F, -CUDART_INF_F, -CUDART_INF_F, -CUDART_INF_F};
        int ci = 0;
        if (have) { ci = col[e2]; edge_logits(ea, s_aew, e2, ci, a1h, lg); }
#pragma unroll
        for (int h = 0; h < 4; h++) {
            float mm = lg[h];
#pragma unroll
            for (int off = 16; off >= 1; off >>= 1)
                mm = fmaxf(mm, __shfl_xor_sync(0xffffffffu, mm, off));
            float ex = have ? __expf(lg[h] - mm) : 0.f;
            float ssum = ex;
#pragma unroll
            for (int off = 16; off >= 1; off >>= 1)
                ssum += __shfl_xor_sync(0xffffffffu, ssum, off);
            float iv = 1.f / (ssum + 1e-16f);
            swp[lane * 4 + h] = ex * iv;
        }
        scp[lane] = ci;
        m[0] = 0.f;
    } else {
        float mm[4] = {-CUDART_INF_F, -CUDART_INF_F, -CUDART_INF_F, -CUDART_INF_F};
        float s[4] = {0.f, 0.f, 0.f, 0.f};
        for (int base = start; base < end; base += 32) {
            int e2 = base + lane;
            if (e2 < end) {
                int ci = col[e2];
                float lg[4];
                edge_logits(ea, s_aew, e2, ci, a1h, lg);
                *(float4*)(g_lg + (size_t)e2 * 4) = make_float4(lg[0], lg[1], lg[2], lg[3]);
#pragma unroll
                for (int h = 0; h < 4; h++) {
                    if (lg[h] > mm[h]) { s[h] = s[h] * __expf(mm[h] - lg[h]) + 1.f; mm[h] = lg[h]; }
                    else               { s[h] += __expf(lg[h] - mm[h]); }
                }
            }
        }
#pragma unroll
        for (int off = 16; off >= 1; off >>= 1) {
#pragma unroll
            for (int h = 0; h < 4; h++) {
                float om = __shfl_xor_sync(0xffffffffu, mm[h], off);
                float os = __shfl_xor_sync(0xffffffffu, s[h], off);
                float nm = fmaxf(mm[h], om);
                float t = (s[h] > 0.f ? s[h] * __expf(mm[h] - nm) : 0.f)
                        + (os > 0.f ? os * __expf(om - nm) : 0.f);
                mm[h] = nm; s[h] = t;
            }
        }
#pragma unroll
        for (int h = 0; h < 4; h++) { m[h] = mm[h]; inv[h] = 1.f / (s[h] + 1e-16f); }
    }

    float4 acc[4];
#pragma unroll
    for (int h = 0; h < 4; h++) acc[h] = make_float4(0.f, 0.f, 0.f, 0.f);
    float acce[4] = {0.f, 0.f, 0.f, 0.f};

    for (int base = start; base < end; base += 32) {
        int cnt = min(32, end - base);
        if (deg > 32) {
            int e2 = base + lane;
            __syncwarp();
            if (e2 < end) {
                float4 lgv = *(const float4*)(g_lg + (size_t)e2 * 4);
                swp[lane * 4 + 0] = __expf(lgv.x - m[0]) * inv[0];
                swp[lane * 4 + 1] = __expf(lgv.y - m[1]) * inv[1];
                swp[lane * 4 + 2] = __expf(lgv.z - m[2]) * inv[2];
                swp[lane * 4 + 3] = __expf(lgv.w - m[3]) * inv[3];
                scp[lane] = col[e2];
            }
        }
        __syncwarp();
#pragma unroll 4
        for (int j = 0; j < cnt; j++) {
            int cj = scp[j];
            float4 wv = *(const float4*)(swp + j * 4);
            float4 xv = *(const float4*)(x + (size_t)cj * 128 + lane * 4);
            acc[0].x += wv.x * xv.x; acc[0].y += wv.x * xv.y; acc[0].z += wv.x * xv.z; acc[0].w += wv.x * xv.w;
            acc[1].x += wv.y * xv.x; acc[1].y += wv.y * xv.y; acc[1].z += wv.y * xv.z; acc[1].w += wv.y * xv.w;
            acc[2].x += wv.z * xv.x; acc[2].y += wv.z * xv.y; acc[2].z += wv.z * xv.z; acc[2].w += wv.z * xv.w;
            acc[3].x += wv.w * xv.x; acc[3].y += wv.w * xv.y; acc[3].z += wv.w * xv.z; acc[3].w += wv.w * xv.w;
            if (lane < 16) {
                float eav = ea[(size_t)(base + j) * 16 + lane];
                acce[0] += wv.x * eav; acce[1] += wv.y * eav;
                acce[2] += wv.z * eav; acce[3] += wv.w * eav;
            }
        }
    }
    size_t ob = (size_t)nd * (NH * IN_DIM);
#pragma unroll
    for (int h = 0; h < 4; h++)
        *(float4*)(g_xobj + ob + h * 128 + lane * 4) = acc[h];
    if (lane < 16) {
#pragma unroll
        for (int h = 0; h < 4; h++)
            g_xe[(size_t)nd * 64 + h * 16 + lane] = acce[h];
    }
}

// ---------------- K3: MLP layer 1 + ReLU + BN stats (1024 thr) ----------------
#define SF_STRIDE 274
#define K3_SMEM ((F_MLP * OUT_H + 128 * SF_STRIDE + 4096) * 4)
__global__ void __launch_bounds__(1024) k_mlp1(const float* __restrict__ x,
                                               const float* __restrict__ b1, int n) {
    extern __shared__ float smem[];
    float* sW = smem;                        // [136 fp][128] lane-contiguous
    float* sF = smem + F_MLP * OUT_H;        // [128 node][274]
    float* sRed = sF + 128 * SF_STRIDE;      // [32 warp][64] x2
    int h = blockIdx.y;
    int n0 = blockIdx.x * 128;
    int tid = threadIdx.x;

    const float* w1p = g_w1p + (size_t)h * (F_MLP * OUT_H);
    for (int i = tid; i < F_MLP * OUT_H; i += 1024) sW[i] = w1p[i];
    for (int i = tid; i < 128 * F_MLP; i += 1024) {
        int nl = i / F_MLP, f = i - nl * F_MLP;
        int nd = n0 + nl;
        float v = 0.f;
        if (nd < n) {
            if (f < 128)      v = x[(size_t)nd * 128 + f];
            else if (f < 256) v = g_xobj[(size_t)nd * 512 + h * 128 + (f - 128)];
            else              v = g_xe[(size_t)nd * 64 + h * 16 + (f - 256)];
        }
        sF[nl * SF_STRIDE + f] = v;
    }
    __syncthreads();

    int to = tid & 15, tn = tid >> 4;        // tn: 0..63 -> 2 nodes; to: 4 outs
    unsigned long long acc[2][4];
#pragma unroll
    for (int i = 0; i < 2; i++)
#pragma unroll
        for (int o = 0; o < 4; o++) acc[i][o] = 0ull;
    const float* fb = sF + tn * 2 * SF_STRIDE;
    const float* wb = sW + to * 4;
#pragma unroll 2
    for (int fp = 0; fp < F_MLP / 2; fp++) {
        ulonglong2 wA = *(const ulonglong2*)(wb + fp * 128);        // o=4to,4to+1
        ulonglong2 wB = *(const ulonglong2*)(wb + fp * 128 + 64);   // o=4to+2,4to+3
#pragma unroll
        for (int i = 0; i < 2; i++) {
            unsigned long long fv = *(const unsigned long long*)(fb + i * SF_STRIDE + 2 * fp);
            ffma2(acc[i][0], fv, wA.x);
            ffma2(acc[i][1], fv, wA.y);
            ffma2(acc[i][2], fv, wB.x);
            ffma2(acc[i][3], fv, wB.y);
        }
    }
    float4 b1q = *(const float4*)(b1 + h * 64 + to * 4);
    float ps[4] = {0.f, 0.f, 0.f, 0.f}, pq[4] = {0.f, 0.f, 0.f, 0.f};
#pragma unroll
    for (int i = 0; i < 2; i++) {
        float v[4];
#pragma unroll
        for (int o = 0; o < 4; o++) {
            float lo, hi; unpack2(acc[i][o], lo, hi);
            v[o] = lo + hi;
        }
        v[0] = fmaxf(v[0] + b1q.x, 0.f); v[1] = fmaxf(v[1] + b1q.y, 0.f);
        v[2] = fmaxf(v[2] + b1q.z, 0.f); v[3] = fmaxf(v[3] + b1q.w, 0.f);
        int nd = n0 + tn * 2 + i;
        if (nd < n) {
            *(float4*)(g_h1 + ((size_t)nd * 4 + h) * 64 + to * 4) = make_float4(v[0], v[1], v[2], v[3]);
#pragma unroll
            for (int o = 0; o < 4; o++) { ps[o] += v[o]; pq[o] += v[o] * v[o]; }
        }
    }
#pragma unroll
    for (int j = 0; j < 4; j++) {
        ps[j] += __shfl_xor_sync(0xffffffffu, ps[j], 16);
        pq[j] += __shfl_xor_sync(0xffffffffu, pq[j], 16);
    }
    int warp = tid >> 5;
    if ((tid & 31) < 16) {
#pragma unroll
        for (int j = 0; j < 4; j++) {
            sRed[warp * 64 + to * 4 + j] = ps[j];
            sRed[2048 + warp * 64 + to * 4 + j] = pq[j];
        }
    }
    __syncthreads();
    if (tid < 64) {
        float s1 = 0.f, s2 = 0.f;
#pragma unroll 4
        for (int w2i = 0; w2i < 32; w2i++) {
            s1 += sRed[w2i * 64 + tid];
            s2 += sRed[2048 + w2i * 64 + tid];
        }
        atomicAdd(&g_sum[h * 64 + tid], s1);
        atomicAdd(&g_sqsum[h * 64 + tid], s2);
    }
}

// ---------------- K4: finalize BN stats ---------------------------------------
__global__ void k_stats(const float* __restrict__ gamma, const float* __restrict__ beta, int n) {
    int i = threadIdx.x;   // 256
    float inv_n = 1.f / (float)n;
    float mu = g_sum[i] * inv_n;
    float var = g_sqsum[i] * inv_n - mu * mu;
    float r = rsqrtf(var + 1e-5f);
    float a = r * gamma[i];
    g_a[i] = a;
    g_c[i] = beta[i] - mu * a;
}

// ---------------- K5: BN apply + MLP layer 2 (1024 thr) -----------------------
#define SH_STRIDE 66
#define K5_SMEM ((4096 + 128 * SH_STRIDE + 128) * 4)
__global__ void __launch_bounds__(1024) k_mlp2(const float* __restrict__ b2,
                                               float* __restrict__ out, int n) {
    extern __shared__ float smem[];
    float* sW = smem;              // [32 op][128] lane-contiguous
    float* sH = smem + 4096;       // [128 node][66]
    float* sAC = sH + 128 * SH_STRIDE;  // a[64], c[64]
    int h = blockIdx.y;
    int n0 = blockIdx.x * 128;
    int tid = threadIdx.x;
    if (tid < 64)       sAC[tid] = g_a[h * 64 + tid];
    else if (tid < 128) sAC[tid] = g_c[h * 64 + tid - 64];
    for (int i = tid; i < 4096; i += 1024) sW[i] = g_w2p[h * 4096 + i];
    __syncthreads();
    for (int i = tid; i < 128 * 64; i += 1024) {
        int nl = i >> 6, o = i & 63;
        int nd = n0 + nl;
        float v = 0.f;
        if (nd < n) v = g_h1[((size_t)nd * 4 + h) * 64 + o] * sAC[o] + sAC[64 + o];
        sH[nl * SH_STRIDE + o] = v;
    }
    __syncthreads();
    int to = tid & 15, tn = tid >> 4;
    unsigned long long acc[2][4];
#pragma unroll
    for (int i = 0; i < 2; i++)
#pragma unroll
        for (int o = 0; o < 4; o++) acc[i][o] = 0ull;
    const float* hb = sH + tn * 2 * SH_STRIDE;
    const float* wb = sW + to * 4;
#pragma unroll 4
    for (int op = 0; op < 32; op++) {
        ulonglong2 wA = *(const ulonglong2*)(wb + op * 128);
        ulonglong2 wB = *(const ulonglong2*)(wb + op * 128 + 64);
#pragma unroll
        for (int i = 0; i < 2; i++) {
            unsigned long long fv = *(const unsigned long long*)(hb + i * SH_STRIDE + 2 * op);
            ffma2(acc[i][0], fv, wA.x);
            ffma2(acc[i][1], fv, wA.y);
            ffma2(acc[i][2], fv, wB.x);
            ffma2(acc[i][3], fv, wB.y);
        }
    }
    float4 b2q = *(const float4*)(b2 + h * 64 + to * 4);
#pragma unroll
    for (int i = 0; i < 2; i++) {
        int nd = n0 + tn * 2 + i;
        if (nd < n) {
            float v[4];
#pragma unroll
            for (int o = 0; o < 4; o++) {
                float lo, hi; unpack2(acc[i][o], lo, hi);
                v[o] = lo + hi;
            }
            *(float4*)(out + (size_t)nd * 256 + h * 64 + to * 4) =
                make_float4(v[0] + b2q.x, v[1] + b2q.y, v[2] + b2q.z, v[3] + b2q.w);
        }
    }
}

// ---------------- launch ------------------------------------------------------
extern "C" void kernel_launch(void* const* d_in, const int* in_sizes, int n_in,
                              void* d_out, int out_size) {
    const float* x     = (const float*)d_in[0];
    const int*   row   = (const int*)d_in[1];
    const int*   col   = (const int*)d_in[2];
    const float* ea    = (const float*)d_in[3];
    const float* a1w   = (const float*)d_in[4];
    const float* a2w   = (const float*)d_in[5];
    const float* aew   = (const float*)d_in[6];
    const float* w1    = (const float*)d_in[7];
    const float* b1    = (const float*)d_in[8];
    const float* gamma = (const float*)d_in[9];
    const float* beta  = (const float*)d_in[10];
    const float* w2    = (const float*)d_in[11];
    const float* b2    = (const float*)d_in[12];
    float* out = (float*)d_out;

    int n = in_sizes[0] / IN_DIM;
    int e = in_sizes[1];

    cudaFuncSetAttribute(k_mlp1, cudaFuncAttributeMaxDynamicSharedMemorySize, K3_SMEM);
    cudaFuncSetAttribute(k_mlp2, cudaFuncAttributeMaxDynamicSharedMemorySize, K5_SMEM);

    k_rowptr<<<(n + 256) / 256, 256>>>(row, n, e);
    k_nodelogits<<<(n + 7) / 8, 256>>>(x, a1w, a2w, n);
    k_pre<<<4, 256>>>(w1, w2);
    k_edge<<<(n + 7) / 8, 256>>>(x, col, ea, aew, n);
    dim3 g3((n + 127) / 128, 4);
    k_mlp1<<<g3, 1024, K3_SMEM>>>(x, b1, n);
    k_stats<<<1, 256>>>(gamma, beta, n);
    k_mlp2<<<g3, 1024, K5_SMEM>>>(b2, out, n);
}

// round 7
// speedup vs baseline: 1.5217x; 1.2160x over previous
#include <cuda_runtime.h>
#include <cuda_bf16.h>
#include <math_constants.h>
#include <cstdint>

#define MAXN 100000
#define MAXE 1600000
#define IN_DIM 128
#define EDGE_DIM 16
#define NH 4
#define OUT_H 64
#define F_MLP 272   // 2*128+16

// ---------------- device scratch ----------------------------------------------
__device__ int   g_rowptr[MAXN + 1];
__device__ float g_attn12[(size_t)MAXN * 8];
__device__ float g_lg[(size_t)MAXE * 4];
__device__ float g_xobj[(size_t)MAXN * NH * IN_DIM];
__device__ float g_xe[(size_t)MAXN * NH * EDGE_DIM];
__device__ float g_h1[(size_t)MAXN * NH * OUT_H];      // [n][h][64] = [n][256]
__device__ float g_sum[NH * OUT_H];
__device__ float g_sqsum[NH * OUT_H];
__device__ float g_a[NH * OUT_H];
__device__ float g_c[NH * OUT_H];

// ---------------- smem address helper ------------------------------------------
__device__ __forceinline__ uint32_t smem_u32(const void* p) {
    uint32_t a;
    asm("{ .reg .u64 t; cvta.to.shared.u64 t, %1; cvt.u32.u64 %0, t; }" : "=r"(a) : "l"(p));
    return a;
}

// ---------------- mma.sync bf16 helpers (sm_80+, works on plain sm_103) --------
__device__ __forceinline__ void ldsm4(uint32_t* r, uint32_t a) {
    asm volatile("ldmatrix.sync.aligned.m8n8.x4.shared.b16 {%0,%1,%2,%3}, [%4];"
        : "=r"(r[0]), "=r"(r[1]), "=r"(r[2]), "=r"(r[3]) : "r"(a));
}
__device__ __forceinline__ void ldsm2(uint32_t* r, uint32_t a) {
    asm volatile("ldmatrix.sync.aligned.m8n8.x2.shared.b16 {%0,%1}, [%2];"
        : "=r"(r[0]), "=r"(r[1]) : "r"(a));
}
__device__ __forceinline__ void mma_bf16(float* c, const uint32_t* a,
                                         uint32_t b0, uint32_t b1) {
    asm volatile("mma.sync.aligned.m16n8k16.row.col.f32.bf16.bf16.f32 "
        "{%0,%1,%2,%3}, {%4,%5,%6,%7}, {%8,%9}, {%0,%1,%2,%3};"
        : "+f"(c[0]), "+f"(c[1]), "+f"(c[2]), "+f"(c[3])
        : "r"(a[0]), "r"(a[1]), "r"(a[2]), "r"(a[3]), "r"(b0), "r"(b1));
}

// One warp: accumulate 32x32 C tile from A[32 x 16*KSTEPS], B[32 x 16*KSTEPS].
// aBase/bBase already include warp tile offsets; strides in bf16 elements.
template<int KSTEPS, int SA, int SB>
__device__ __forceinline__ void mma_block(float c[2][4][4], uint32_t aBase,
                                          uint32_t bBase, int lane) {
    uint32_t aRow = aBase + (uint32_t)(((lane & 15) * SA + ((lane >> 4) << 3)) * 2);
    uint32_t bRow = bBase + (uint32_t)(((lane & 7) * SB + (((lane >> 3) & 1) << 3)) * 2);
#pragma unroll
    for (int ks = 0; ks < KSTEPS; ks++) {
        uint32_t a0[4], a1[4];
        ldsm4(a0, aRow + ks * 32);
        ldsm4(a1, aRow + 16 * SA * 2 + ks * 32);
#pragma unroll
        for (int ni = 0; ni < 4; ni++) {
            uint32_t b[2];
            ldsm2(b, bRow + ni * 8 * SB * 2 + ks * 32);
            mma_bf16(c[0][ni], a0, b[0], b[1]);
            mma_bf16(c[1][ni], a1, b[0], b[1]);
        }
    }
}

// split fp32 float4 -> bf16 hi pair-words + lo pair-words
__device__ __forceinline__ void split4(float4 v, uint32_t& hi01, uint32_t& hi23,
                                       uint32_t& lo01, uint32_t& lo23) {
    uint32_t b0 = __float_as_uint(v.x), b1 = __float_as_uint(v.y);
    uint32_t b2 = __float_as_uint(v.z), b3 = __float_as_uint(v.w);
    hi01 = __byte_perm(b0, b1, 0x7632);
    hi23 = __byte_perm(b2, b3, 0x7632);
    float l0 = v.x - __uint_as_float(b0 & 0xffff0000u);
    float l1 = v.y - __uint_as_float(b1 & 0xffff0000u);
    float l2 = v.z - __uint_as_float(b2 & 0xffff0000u);
    float l3 = v.w - __uint_as_float(b3 & 0xffff0000u);
    __nv_bfloat162 p01 = __floats2bfloat162_rn(l0, l1);
    __nv_bfloat162 p23 = __floats2bfloat162_rn(l2, l3);
    lo01 = *reinterpret_cast<uint32_t*>(&p01);
    lo23 = *reinterpret_cast<uint32_t*>(&p23);
}

// ---------------- K0: CSR row pointers ----------------------------------------
__global__ void k_rowptr(const int* __restrict__ row, int n, int e) {
    int i = blockIdx.x * blockDim.x + threadIdx.x;
    if (i > n) return;
    int lo = 0, hi = e;
    while (lo < hi) { int mid = (lo + hi) >> 1; if (row[mid] < i) lo = mid + 1; else hi = mid; }
    g_rowptr[i] = lo;
}

// ---------------- K1: per-node attention logits -------------------------------
__global__ void k_nodelogits(const float* __restrict__ x, const float* __restrict__ a1w,
                             const float* __restrict__ a2w, int n) {
    __shared__ float sw[8 * 128];
    int tid = threadIdx.x;
    for (int i = tid; i < 512; i += 256) { sw[i] = a1w[i]; sw[512 + i] = a2w[i]; }
    __syncthreads();
    int warp = tid >> 5, lane = tid & 31;
    int nd = blockIdx.x * 8 + warp;
    if (nd >= n) return;
    float4 xv = *(const float4*)(x + (size_t)nd * 128 + lane * 4);
#pragma unroll
    for (int k = 0; k < 8; k++) {
        float4 wv = *(const float4*)(sw + k * 128 + lane * 4);
        float p = xv.x * wv.x + xv.y * wv.y + xv.z * wv.z + xv.w * wv.w;
        p += __shfl_xor_sync(0xffffffffu, p, 16);
        p += __shfl_xor_sync(0xffffffffu, p, 8);
        p += __shfl_xor_sync(0xffffffffu, p, 4);
        p += __shfl_xor_sync(0xffffffffu, p, 2);
        p += __shfl_xor_sync(0xffffffffu, p, 1);
        if (lane == 0) g_attn12[(size_t)nd * 8 + k] = p;
    }
}

// ---------------- K_zero: BN stat accumulators --------------------------------
__global__ void k_zero() {
    int i = threadIdx.x;   // 256
    g_sum[i] = 0.f; g_sqsum[i] = 0.f;
}

// ---------------- K2: edge softmax + aggregation (warp per node) --------------
__device__ __forceinline__ void edge_logits(const float* __restrict__ ea,
                                            const float* s_aew, int e2, int ci,
                                            const float* a1h, float* lg) {
    const float4* ep = (const float4*)(ea + (size_t)e2 * 16);
    float4 q0 = ep[0], q1 = ep[1], q2 = ep[2], q3 = ep[3];
    float4 a2v = *(const float4*)(g_attn12 + (size_t)ci * 8 + 4);
    float a2a[4] = {a2v.x, a2v.y, a2v.z, a2v.w};
#pragma unroll
    for (int h = 0; h < 4; h++) {
        const float* wq = s_aew + h * 16;
        float d = q0.x * wq[0] + q0.y * wq[1] + q0.z * wq[2] + q0.w * wq[3]
                + q1.x * wq[4] + q1.y * wq[5] + q1.z * wq[6] + q1.w * wq[7]
                + q2.x * wq[8] + q2.y * wq[9] + q2.z * wq[10] + q2.w * wq[11]
                + q3.x * wq[12] + q3.y * wq[13] + q3.z * wq[14] + q3.w * wq[15];
        lg[h] = (a1h[h] + a2a[h] + d) * 0.125f;
    }
}

__global__ void __launch_bounds__(256) k_edge(const float* __restrict__ x,
                                              const int* __restrict__ col,
                                              const float* __restrict__ ea,
                                              const float* __restrict__ aew, int n) {
    __shared__ float s_aew[64];
    __shared__ float s_w[8 * 32 * 4];
    __shared__ int   s_c[8 * 32];
    int tid = threadIdx.x;
    if (tid < 64) s_aew[tid] = aew[tid];
    __syncthreads();
    int warp = tid >> 5, lane = tid & 31;
    int nd = blockIdx.x * 8 + warp;
    if (nd >= n) return;
    int start = g_rowptr[nd], end = g_rowptr[nd + 1];
    int deg = end - start;
    float a1h[4];
    {
        float4 a1v = *(const float4*)(g_attn12 + (size_t)nd * 8);
        a1h[0] = a1v.x; a1h[1] = a1v.y; a1h[2] = a1v.z; a1h[3] = a1v.w;
    }
    float* swp = s_w + warp * 128;
    int*   scp = s_c + warp * 32;

    float m[4], inv[4];

    if (deg <= 32) {
        int e2 = start + lane;
        bool have = (e2 < end);
        float lg[4] = {-CUDART_INF_F, -CUDART_INF_F, -CUDART_INF_F, -CUDART_INF_F};
        int ci = 0;
        if (have) { ci = col[e2]; edge_logits(ea, s_aew, e2, ci, a1h, lg); }
#pragma unroll
        for (int h = 0; h < 4; h++) {
            float mm = lg[h];
#pragma unroll
            for (int off = 16; off >= 1; off >>= 1)
                mm = fmaxf(mm, __shfl_xor_sync(0xffffffffu, mm, off));
            float ex = have ? __expf(lg[h] - mm) : 0.f;
            float ssum = ex;
#pragma unroll
            for (int off = 16; off >= 1; off >>= 1)
                ssum += __shfl_xor_sync(0xffffffffu, ssum, off);
            float iv = 1.f / (ssum + 1e-16f);
            swp[lane * 4 + h] = ex * iv;
        }
        scp[lane] = ci;
        m[0] = 0.f;
    } else {
        float mm[4] = {-CUDART_INF_F, -CUDART_INF_F, -CUDART_INF_F, -CUDART_INF_F};
        float s[4] = {0.f, 0.f, 0.f, 0.f};
        for (int base = start; base < end; base += 32) {
            int e2 = base + lane;
            if (e2 < end) {
                int ci = col[e2];
                float lg[4];
                edge_logits(ea, s_aew, e2, ci, a1h, lg);
                *(float4*)(g_lg + (size_t)e2 * 4) = make_float4(lg[0], lg[1], lg[2], lg[3]);
#pragma unroll
                for (int h = 0; h < 4; h++) {
                    if (lg[h] > mm[h]) { s[h] = s[h] * __expf(mm[h] - lg[h]) + 1.f; mm[h] = lg[h]; }
                    else               { s[h] += __expf(lg[h] - mm[h]); }
                }
            }
        }
#pragma unroll
        for (int off = 16; off >= 1; off >>= 1) {
#pragma unroll
            for (int h = 0; h < 4; h++) {
                float om = __shfl_xor_sync(0xffffffffu, mm[h], off);
                float os = __shfl_xor_sync(0xffffffffu, s[h], off);
                float nm = fmaxf(mm[h], om);
                float t = (s[h] > 0.f ? s[h] * __expf(mm[h] - nm) : 0.f)
                        + (os > 0.f ? os * __expf(om - nm) : 0.f);
                mm[h] = nm; s[h] = t;
            }
        }
#pragma unroll
        for (int h = 0; h < 4; h++) { m[h] = mm[h]; inv[h] = 1.f / (s[h] + 1e-16f); }
    }

    float4 acc[4];
#pragma unroll
    for (int h = 0; h < 4; h++) acc[h] = make_float4(0.f, 0.f, 0.f, 0.f);
    float acce[4] = {0.f, 0.f, 0.f, 0.f};

    for (int base = start; base < end; base += 32) {
        int cnt = min(32, end - base);
        if (deg > 32) {
            int e2 = base + lane;
            __syncwarp();
            if (e2 < end) {
                float4 lgv = *(const float4*)(g_lg + (size_t)e2 * 4);
                swp[lane * 4 + 0] = __expf(lgv.x - m[0]) * inv[0];
                swp[lane * 4 + 1] = __expf(lgv.y - m[1]) * inv[1];
                swp[lane * 4 + 2] = __expf(lgv.z - m[2]) * inv[2];
                swp[lane * 4 + 3] = __expf(lgv.w - m[3]) * inv[3];
                scp[lane] = col[e2];
            }
        }
        __syncwarp();
#pragma unroll 4
        for (int j = 0; j < cnt; j++) {
            int cj = scp[j];
            float4 wv = *(const float4*)(swp + j * 4);
            float4 xv = *(const float4*)(x + (size_t)cj * 128 + lane * 4);
            acc[0].x += wv.x * xv.x; acc[0].y += wv.x * xv.y; acc[0].z += wv.x * xv.z; acc[0].w += wv.x * xv.w;
            acc[1].x += wv.y * xv.x; acc[1].y += wv.y * xv.y; acc[1].z += wv.y * xv.z; acc[1].w += wv.y * xv.w;
            acc[2].x += wv.z * xv.x; acc[2].y += wv.z * xv.y; acc[2].z += wv.z * xv.z; acc[2].w += wv.z * xv.w;
            acc[3].x += wv.w * xv.x; acc[3].y += wv.w * xv.y; acc[3].z += wv.w * xv.z; acc[3].w += wv.w * xv.w;
            if (lane < 16) {
                float eav = ea[(size_t)(base + j) * 16 + lane];
                acce[0] += wv.x * eav; acce[1] += wv.y * eav;
                acce[2] += wv.z * eav; acce[3] += wv.w * eav;
            }
        }
    }
    size_t ob = (size_t)nd * (NH * IN_DIM);
#pragma unroll
    for (int h = 0; h < 4; h++)
        *(float4*)(g_xobj + ob + h * 128 + lane * 4) = acc[h];
    if (lane < 16) {
#pragma unroll
        for (int h = 0; h < 4; h++)
            g_xe[(size_t)nd * 64 + h * 16 + lane] = acce[h];
    }
}

// ---------------- K3: MLP layer 1 via mma.sync bf16 3-pass --------------------
// CTA = 128 nodes x 64 outs, one head. 8 warps: 4(M) x 2(N), warp tile 32x32.
#define SA1 280
#define A1HI 0
#define A1LO (128 * SA1 * 2)                 // 71680
#define B1HI (2 * 128 * SA1 * 2)             // 143360
#define B1LO (B1HI + 64 * SA1 * 2)           // 179200
#define MLP1_SMEM (B1LO + 64 * SA1 * 2)      // 215040
__global__ void __launch_bounds__(256) k_mlp1h(const float* __restrict__ x,
                                               const float* __restrict__ w1,
                                               const float* __restrict__ b1, int n) {
    extern __shared__ char smem[];
    uint32_t sb = smem_u32(smem);
    int tid = threadIdx.x, lane = tid & 31, wid = tid >> 5;
    int h = blockIdx.y;
    int n0 = blockIdx.x * 128;

    // fill B: w1[h][o][f] -> bf16 hi/lo [o][f]
    const float* w1h = w1 + (size_t)h * OUT_H * F_MLP;
    for (int i = tid; i < 64 * 68; i += 256) {
        int o = i / 68, f = (i - o * 68) * 4;
        float4 v = *(const float4*)(w1h + o * F_MLP + f);
        uint32_t h01, h23, l01, l23;
        split4(v, h01, h23, l01, l23);
        *(uint2*)(smem + B1HI + (o * SA1 + f) * 2) = make_uint2(h01, h23);
        *(uint2*)(smem + B1LO + (o * SA1 + f) * 2) = make_uint2(l01, l23);
    }
    // fill A: features [node][272] -> bf16 hi/lo
    for (int i = tid; i < 128 * 68; i += 256) {
        int nl = i / 68, f = (i - nl * 68) * 4;
        int nd = n0 + nl;
        float4 v = make_float4(0.f, 0.f, 0.f, 0.f);
        if (nd < n) {
            if (f < 128)      v = *(const float4*)(x + (size_t)nd * 128 + f);
            else if (f < 256) v = *(const float4*)(g_xobj + (size_t)nd * 512 + h * 128 + (f - 128));
            else              v = *(const float4*)(g_xe + (size_t)nd * 64 + h * 16 + (f - 256));
        }
        uint32_t h01, h23, l01, l23;
        split4(v, h01, h23, l01, l23);
        *(uint2*)(smem + A1HI + (nl * SA1 + f) * 2) = make_uint2(h01, h23);
        *(uint2*)(smem + A1LO + (nl * SA1 + f) * 2) = make_uint2(l01, l23);
    }
    __syncthreads();

    float c[2][4][4] = {};
    int wm = wid & 3, wn = wid >> 2;
    uint32_t aH = sb + A1HI + wm * 32 * SA1 * 2;
    uint32_t aL = sb + A1LO + wm * 32 * SA1 * 2;
    uint32_t bH = sb + B1HI + wn * 32 * SA1 * 2;
    uint32_t bL = sb + B1LO + wn * 32 * SA1 * 2;
    mma_block<17, SA1, SA1>(c, aH, bH, lane);
    mma_block<17, SA1, SA1>(c, aH, bL, lane);
    mma_block<17, SA1, SA1>(c, aL, bH, lane);

    // epilogue: bias + ReLU -> g_h1
    const float* bb = b1 + h * 64;
    int g = lane >> 2, tc2 = 2 * (lane & 3);
#pragma unroll
    for (int mi = 0; mi < 2; mi++) {
#pragma unroll
        for (int ni = 0; ni < 4; ni++) {
            int colo = wn * 32 + ni * 8 + tc2;
            float2 bv = *(const float2*)(bb + colo);
            int ndr = n0 + wm * 32 + mi * 16 + g;
            float* dst = g_h1 + (size_t)ndr * 256 + h * 64 + colo;
            if (ndr < n) {
                float2 v = make_float2(fmaxf(c[mi][ni][0] + bv.x, 0.f),
                                       fmaxf(c[mi][ni][1] + bv.y, 0.f));
                *(float2*)dst = v;
            }
            if (ndr + 8 < n) {
                float2 v = make_float2(fmaxf(c[mi][ni][2] + bv.x, 0.f),
                                       fmaxf(c[mi][ni][3] + bv.y, 0.f));
                *(float2*)(dst + 8 * 256) = v;
            }
        }
    }
}

// ---------------- K3b: BN partial sums over g_h1 ------------------------------
__global__ void k_bnsum(int n) {
    int t = threadIdx.x;   // 256 -> (h,o)
    float s = 0.f, q = 0.f;
    for (int nd = blockIdx.x; nd < n; nd += gridDim.x) {
        float v = g_h1[(size_t)nd * 256 + t];
        s += v; q += v * v;
    }
    atomicAdd(&g_sum[t], s);
    atomicAdd(&g_sqsum[t], q);
}

// ---------------- K4: finalize BN stats ---------------------------------------
__global__ void k_stats(const float* __restrict__ gamma, const float* __restrict__ beta, int n) {
    int i = threadIdx.x;   // 256
    float inv_n = 1.f / (float)n;
    float mu = g_sum[i] * inv_n;
    float var = g_sqsum[i] * inv_n - mu * mu;
    float r = rsqrtf(var + 1e-5f);
    float a = r * gamma[i];
    g_a[i] = a;
    g_c[i] = beta[i] - mu * a;
}

// ---------------- K5: BN apply + MLP layer 2 via mma.sync ---------------------
#define SA2 72
#define A2HI 0
#define A2LO (128 * SA2 * 2)                 // 18432
#define B2HI (2 * 128 * SA2 * 2)             // 36864
#define B2LO (B2HI + 64 * SA2 * 2)           // 46080
#define MLP2_SMEM (B2LO + 64 * SA2 * 2)      // 55296
__global__ void __launch_bounds__(256) k_mlp2h(const float* __restrict__ w2,
                                               const float* __restrict__ b2,
                                               float* __restrict__ out, int n) {
    extern __shared__ char smem[];
    uint32_t sb = smem_u32(smem);
    int tid = threadIdx.x, lane = tid & 31, wid = tid >> 5;
    int h = blockIdx.y;
    int n0 = blockIdx.x * 128;

    // fill B: w2[h][p][o]
    const float* w2h = w2 + h * 4096;
    for (int i = tid; i < 64 * 16; i += 256) {
        int p = i >> 4, f = (i & 15) * 4;
        float4 v = *(const float4*)(w2h + p * 64 + f);
        uint32_t h01, h23, l01, l23;
        split4(v, h01, h23, l01, l23);
        *(uint2*)(smem + B2HI + (p * SA2 + f) * 2) = make_uint2(h01, h23);
        *(uint2*)(smem + B2LO + (p * SA2 + f) * 2) = make_uint2(l01, l23);
    }
    // fill A: BN-applied h1
    for (int i = tid; i < 128 * 16; i += 256) {
        int nl = i >> 4, f = (i & 15) * 4;
        int nd = n0 + nl;
        float4 v = make_float4(0.f, 0.f, 0.f, 0.f);
        if (nd < n) {
            float4 hv = *(const float4*)(g_h1 + (size_t)nd * 256 + h * 64 + f);
            float4 av = *(const float4*)(g_a + h * 64 + f);
            float4 cv = *(const float4*)(g_c + h * 64 + f);
            v = make_float4(hv.x * av.x + cv.x, hv.y * av.y + cv.y,
                            hv.z * av.z + cv.z, hv.w * av.w + cv.w);
        }
        uint32_t h01, h23, l01, l23;
        split4(v, h01, h23, l01, l23);
        *(uint2*)(smem + A2HI + (nl * SA2 + f) * 2) = make_uint2(h01, h23);
        *(uint2*)(smem + A2LO + (nl * SA2 + f) * 2) = make_uint2(l01, l23);
    }
    __syncthreads();

    float c[2][4][4] = {};
    int wm = wid & 3, wn = wid >> 2;
    uint32_t aH = sb + A2HI + wm * 32 * SA2 * 2;
    uint32_t aL = sb + A2LO + wm * 32 * SA2 * 2;
    uint32_t bH = sb + B2HI + wn * 32 * SA2 * 2;
    uint32_t bL = sb + B2LO + wn * 32 * SA2 * 2;
    mma_block<4, SA2, SA2>(c, aH, bH, lane);
    mma_block<4, SA2, SA2>(c, aH, bL, lane);
    mma_block<4, SA2, SA2>(c, aL, bH, lane);

    // epilogue: bias -> out
    const float* bb = b2 + h * 64;
    int g = lane >> 2, tc2 = 2 * (lane & 3);
#pragma unroll
    for (int mi = 0; mi < 2; mi++) {
#pragma unroll
        for (int ni = 0; ni < 4; ni++) {
            int colo = wn * 32 + ni * 8 + tc2;
            float2 bv = *(const float2*)(bb + colo);
            int ndr = n0 + wm * 32 + mi * 16 + g;
            float* dst = out + (size_t)ndr * 256 + h * 64 + colo;
            if (ndr < n)
                *(float2*)dst = make_float2(c[mi][ni][0] + bv.x, c[mi][ni][1] + bv.y);
            if (ndr + 8 < n)
                *(float2*)(dst + 8 * 256) =
                    make_float2(c[mi][ni][2] + bv.x, c[mi][ni][3] + bv.y);
        }
    }
}

// ---------------- launch ------------------------------------------------------
extern "C" void kernel_launch(void* const* d_in, const int* in_sizes, int n_in,
                              void* d_out, int out_size) {
    const float* x     = (const float*)d_in[0];
    const int*   row   = (const int*)d_in[1];
    const int*   col   = (const int*)d_in[2];
    const float* ea    = (const float*)d_in[3];
    const float* a1w   = (const float*)d_in[4];
    const float* a2w   = (const float*)d_in[5];
    const float* aew   = (const float*)d_in[6];
    const float* w1    = (const float*)d_in[7];
    const float* b1    = (const float*)d_in[8];
    const float* gamma = (const float*)d_in[9];
    const float* beta  = (const float*)d_in[10];
    const float* w2    = (const float*)d_in[11];
    const float* b2    = (const float*)d_in[12];
    float* out = (float*)d_out;

    int n = in_sizes[0] / IN_DIM;
    int e = in_sizes[1];

    cudaFuncSetAttribute(k_mlp1h, cudaFuncAttributeMaxDynamicSharedMemorySize, MLP1_SMEM);
    cudaFuncSetAttribute(k_mlp2h, cudaFuncAttributeMaxDynamicSharedMemorySize, MLP2_SMEM);

    k_rowptr<<<(n + 256) / 256, 256>>>(row, n, e);
    k_nodelogits<<<(n + 7) / 8, 256>>>(x, a1w, a2w, n);
    k_zero<<<1, 256>>>();
    k_edge<<<(n + 7) / 8, 256>>>(x, col, ea, aew, n);
    dim3 g3((n + 127) / 128, 4);
    k_mlp1h<<<g3, 256, MLP1_SMEM>>>(x, w1, b1, n);
    k_bnsum<<<296, 256>>>(n);
    k_stats<<<1, 256>>>(gamma, beta, n);
    k_mlp2h<<<g3, 256, MLP2_SMEM>>>(w2, b2, out, n);
}

// round 8
// speedup vs baseline: 2.4232x; 1.5924x over previous
#include <cuda_runtime.h>
#include <cuda_bf16.h>
#include <math_constants.h>
#include <cstdint>

#define MAXN 100000
#define MAXE 1600000
#define IN_DIM 128
#define EDGE_DIM 16
#define NH 4
#define OUT_H 64
#define F_MLP 272   // 2*128+16

// ---------------- device scratch ----------------------------------------------
__device__ int   g_rowptr[MAXN + 1];
__device__ float g_attn12[(size_t)MAXN * 8];
__device__ float g_lg[(size_t)MAXE * 4];
__device__ float g_h1[(size_t)MAXN * NH * OUT_H];      // [n][h][64] = [n][256]
__device__ float g_sum[NH * OUT_H];
__device__ float g_sqsum[NH * OUT_H];
__device__ float g_a[NH * OUT_H];
__device__ float g_c[NH * OUT_H];
// bf16 hi/lo pre-split data
__device__ __nv_bfloat16 g_xhi[(size_t)MAXN * 128];
__device__ __nv_bfloat16 g_xlo[(size_t)MAXN * 128];
__device__ __nv_bfloat16 g_obhi[(size_t)MAXN * NH * 128];
__device__ __nv_bfloat16 g_oblo[(size_t)MAXN * NH * 128];
__device__ __nv_bfloat16 g_xehi[(size_t)MAXN * NH * 16];
__device__ __nv_bfloat16 g_xelo[(size_t)MAXN * NH * 16];
__device__ __nv_bfloat16 g_w1s[(size_t)NH * 2 * OUT_H * F_MLP];  // [h][pass][o][272]
__device__ __nv_bfloat16 g_w2s[(size_t)NH * 2 * OUT_H * OUT_H];  // [h][pass][p][64]

// ---------------- helpers ------------------------------------------------------
__device__ __forceinline__ uint32_t smem_u32(const void* p) {
    uint32_t a;
    asm("{ .reg .u64 t; cvta.to.shared.u64 t, %1; cvt.u32.u64 %0, t; }" : "=r"(a) : "l"(p));
    return a;
}
__device__ __forceinline__ void cpa16(uint32_t dst, const void* src) {
    asm volatile("cp.async.cg.shared.global [%0], [%1], 16;" :: "r"(dst), "l"(src));
}
#define CPWAIT() asm volatile("cp.async.commit_group;\n\tcp.async.wait_group 0;" ::: "memory")

__device__ __forceinline__ void ldsm4(uint32_t* r, uint32_t a) {
    asm volatile("ldmatrix.sync.aligned.m8n8.x4.shared.b16 {%0,%1,%2,%3}, [%4];"
        : "=r"(r[0]), "=r"(r[1]), "=r"(r[2]), "=r"(r[3]) : "r"(a));
}
__device__ __forceinline__ void ldsm2(uint32_t* r, uint32_t a) {
    asm volatile("ldmatrix.sync.aligned.m8n8.x2.shared.b16 {%0,%1}, [%2];"
        : "=r"(r[0]), "=r"(r[1]) : "r"(a));
}
__device__ __forceinline__ void mma_bf16(float* c, const uint32_t* a,
                                         uint32_t b0, uint32_t b1) {
    asm volatile("mma.sync.aligned.m16n8k16.row.col.f32.bf16.bf16.f32 "
        "{%0,%1,%2,%3}, {%4,%5,%6,%7}, {%8,%9}, {%0,%1,%2,%3};"
        : "+f"(c[0]), "+f"(c[1]), "+f"(c[2]), "+f"(c[3])
        : "r"(a[0]), "r"(a[1]), "r"(a[2]), "r"(a[3]), "r"(b0), "r"(b1));
}

template<int KSTEPS, int SA, int SB>
__device__ __forceinline__ void mma_block(float c[2][4][4], uint32_t aBase,
                                          uint32_t bBase, int lane) {
    uint32_t aRow = aBase + (uint32_t)(((lane & 15) * SA + ((lane >> 4) << 3)) * 2);
    uint32_t bRow = bBase + (uint32_t)(((lane & 7) * SB + (((lane >> 3) & 1) << 3)) * 2);
#pragma unroll
    for (int ks = 0; ks < KSTEPS; ks++) {
        uint32_t a0[4], a1[4];
        ldsm4(a0, aRow + ks * 32);
        ldsm4(a1, aRow + 16 * SA * 2 + ks * 32);
#pragma unroll
        for (int ni = 0; ni < 4; ni++) {
            uint32_t b[2];
            ldsm2(b, bRow + ni * 8 * SB * 2 + ks * 32);
            mma_bf16(c[0][ni], a0, b[0], b[1]);
            mma_bf16(c[1][ni], a1, b[0], b[1]);
        }
    }
}

// split fp32 float4 -> bf16 hi pair-words + lo pair-words
__device__ __forceinline__ void split4(float4 v, uint32_t& hi01, uint32_t& hi23,
                                       uint32_t& lo01, uint32_t& lo23) {
    uint32_t b0 = __float_as_uint(v.x), b1 = __float_as_uint(v.y);
    uint32_t b2 = __float_as_uint(v.z), b3 = __float_as_uint(v.w);
    hi01 = __byte_perm(b0, b1, 0x7632);
    hi23 = __byte_perm(b2, b3, 0x7632);
    float l0 = v.x - __uint_as_float(b0 & 0xffff0000u);
    float l1 = v.y - __uint_as_float(b1 & 0xffff0000u);
    float l2 = v.z - __uint_as_float(b2 & 0xffff0000u);
    float l3 = v.w - __uint_as_float(b3 & 0xffff0000u);
    __nv_bfloat162 p01 = __floats2bfloat162_rn(l0, l1);
    __nv_bfloat162 p23 = __floats2bfloat162_rn(l2, l3);
    lo01 = *reinterpret_cast<uint32_t*>(&p01);
    lo23 = *reinterpret_cast<uint32_t*>(&p23);
}

// ---------------- K0: CSR row pointers ----------------------------------------
__global__ void k_rowptr(const int* __restrict__ row, int n, int e) {
    int i = blockIdx.x * blockDim.x + threadIdx.x;
    if (i > n) return;
    int lo = 0, hi = e;
    while (lo < hi) { int mid = (lo + hi) >> 1; if (row[mid] < i) lo = mid + 1; else hi = mid; }
    g_rowptr[i] = lo;
}

// ---------------- K1: per-node attention logits -------------------------------
__global__ void k_nodelogits(const float* __restrict__ x, const float* __restrict__ a1w,
                             const float* __restrict__ a2w, int n) {
    __shared__ float sw[8 * 128];
    int tid = threadIdx.x;
    for (int i = tid; i < 512; i += 256) { sw[i] = a1w[i]; sw[512 + i] = a2w[i]; }
    __syncthreads();
    int warp = tid >> 5, lane = tid & 31;
    int nd = blockIdx.x * 8 + warp;
    if (nd >= n) return;
    float4 xv = *(const float4*)(x + (size_t)nd * 128 + lane * 4);
#pragma unroll
    for (int k = 0; k < 8; k++) {
        float4 wv = *(const float4*)(sw + k * 128 + lane * 4);
        float p = xv.x * wv.x + xv.y * wv.y + xv.z * wv.z + xv.w * wv.w;
        p += __shfl_xor_sync(0xffffffffu, p, 16);
        p += __shfl_xor_sync(0xffffffffu, p, 8);
        p += __shfl_xor_sync(0xffffffffu, p, 4);
        p += __shfl_xor_sync(0xffffffffu, p, 2);
        p += __shfl_xor_sync(0xffffffffu, p, 1);
        if (lane == 0) g_attn12[(size_t)nd * 8 + k] = p;
    }
}

// ---------------- K_pre: pre-split w1/w2 to bf16 hi/lo; zero stats ------------
__global__ void k_pre(const float* __restrict__ w1, const float* __restrict__ w2) {
    int h = blockIdx.x, tid = threadIdx.x;   // 4 blocks x 256
    for (int i = tid; i < OUT_H * 68; i += 256) {
        int o = i / 68, f = (i - o * 68) * 4;
        float4 v = *(const float4*)(w1 + ((size_t)h * OUT_H + o) * F_MLP + f);
        uint32_t h01, h23, l01, l23;
        split4(v, h01, h23, l01, l23);
        *(uint2*)(g_w1s + ((size_t)(h * 2 + 0) * OUT_H + o) * F_MLP + f) = make_uint2(h01, h23);
        *(uint2*)(g_w1s + ((size_t)(h * 2 + 1) * OUT_H + o) * F_MLP + f) = make_uint2(l01, l23);
    }
    for (int i = tid; i < OUT_H * 16; i += 256) {
        int p = i >> 4, f = (i & 15) * 4;
        float4 v = *(const float4*)(w2 + (size_t)h * 4096 + p * 64 + f);
        uint32_t h01, h23, l01, l23;
        split4(v, h01, h23, l01, l23);
        *(uint2*)(g_w2s + ((size_t)(h * 2 + 0) * OUT_H + p) * 64 + f) = make_uint2(h01, h23);
        *(uint2*)(g_w2s + ((size_t)(h * 2 + 1) * OUT_H + p) * 64 + f) = make_uint2(l01, l23);
    }
    if (h == 0) { g_sum[tid] = 0.f; g_sqsum[tid] = 0.f; }
}

// ---------------- K_xsplit: pre-split x ---------------------------------------
__global__ void k_xsplit(const float* __restrict__ x, int n) {
    size_t i = (size_t)blockIdx.x * blockDim.x + threadIdx.x;
    if (i * 4 >= (size_t)n * 128) return;
    float4 v = *(const float4*)(x + i * 4);
    uint32_t h01, h23, l01, l23;
    split4(v, h01, h23, l01, l23);
    *(uint2*)(g_xhi + i * 4) = make_uint2(h01, h23);
    *(uint2*)(g_xlo + i * 4) = make_uint2(l01, l23);
}

// ---------------- K2: edge softmax + aggregation (warp per node) --------------
__device__ __forceinline__ void edge_logits(const float* __restrict__ ea,
                                            const float* s_aew, int e2, int ci,
                                            const float* a1h, float* lg) {
    const float4* ep = (const float4*)(ea + (size_t)e2 * 16);
    float4 q0 = ep[0], q1 = ep[1], q2 = ep[2], q3 = ep[3];
    float4 a2v = *(const float4*)(g_attn12 + (size_t)ci * 8 + 4);
    float a2a[4] = {a2v.x, a2v.y, a2v.z, a2v.w};
#pragma unroll
    for (int h = 0; h < 4; h++) {
        const float* wq = s_aew + h * 16;
        float d = q0.x * wq[0] + q0.y * wq[1] + q0.z * wq[2] + q0.w * wq[3]
                + q1.x * wq[4] + q1.y * wq[5] + q1.z * wq[6] + q1.w * wq[7]
                + q2.x * wq[8] + q2.y * wq[9] + q2.z * wq[10] + q2.w * wq[11]
                + q3.x * wq[12] + q3.y * wq[13] + q3.z * wq[14] + q3.w * wq[15];
        lg[h] = (a1h[h] + a2a[h] + d) * 0.125f;
    }
}

__global__ void __launch_bounds__(256) k_edge(const float* __restrict__ x,
                                              const int* __restrict__ col,
                                              const float* __restrict__ ea,
                                              const float* __restrict__ aew, int n) {
    __shared__ float s_aew[64];
    __shared__ float s_w[8 * 32 * 4];
    __shared__ int   s_c[8 * 32];
    int tid = threadIdx.x;
    if (tid < 64) s_aew[tid] = aew[tid];
    __syncthreads();
    int warp = tid >> 5, lane = tid & 31;
    int nd = blockIdx.x * 8 + warp;
    if (nd >= n) return;
    int start = g_rowptr[nd], end = g_rowptr[nd + 1];
    int deg = end - start;
    float a1h[4];
    {
        float4 a1v = *(const float4*)(g_attn12 + (size_t)nd * 8);
        a1h[0] = a1v.x; a1h[1] = a1v.y; a1h[2] = a1v.z; a1h[3] = a1v.w;
    }
    float* swp = s_w + warp * 128;
    int*   scp = s_c + warp * 32;

    float m[4], inv[4];

    if (deg <= 32) {
        int e2 = start + lane;
        bool have = (e2 < end);
        float lg[4] = {-CUDART_INF_F, -CUDART_INF_F, -CUDART_INF_F, -CUDART_INF_F};
        int ci = 0;
        if (have) { ci = col[e2]; edge_logits(ea, s_aew, e2, ci, a1h, lg); }
#pragma unroll
        for (int h = 0; h < 4; h++) {
            float mm = lg[h];
#pragma unroll
            for (int off = 16; off >= 1; off >>= 1)
                mm = fmaxf(mm, __shfl_xor_sync(0xffffffffu, mm, off));
            float ex = have ? __expf(lg[h] - mm) : 0.f;
            float ssum = ex;
#pragma unroll
            for (int off = 16; off >= 1; off >>= 1)
                ssum += __shfl_xor_sync(0xffffffffu, ssum, off);
            float iv = 1.f / (ssum + 1e-16f);
            swp[lane * 4 + h] = ex * iv;
        }
        scp[lane] = ci;
        m[0] = 0.f;
    } else {
        float mm[4] = {-CUDART_INF_F, -CUDART_INF_F, -CUDART_INF_F, -CUDART_INF_F};
        float s[4] = {0.f, 0.f, 0.f, 0.f};
        for (int base = start; base < end; base += 32) {
            int e2 = base + lane;
            if (e2 < end) {
                int ci = col[e2];
                float lg[4];
                edge_logits(ea, s_aew, e2, ci, a1h, lg);
                *(float4*)(g_lg + (size_t)e2 * 4) = make_float4(lg[0], lg[1], lg[2], lg[3]);
#pragma unroll
                for (int h = 0; h < 4; h++) {
                    if (lg[h] > mm[h]) { s[h] = s[h] * __expf(mm[h] - lg[h]) + 1.f; mm[h] = lg[h]; }
                    else               { s[h] += __expf(lg[h] - mm[h]); }
                }
            }
        }
#pragma unroll
        for (int off = 16; off >= 1; off >>= 1) {
#pragma unroll
            for (int h = 0; h < 4; h++) {
                float om = __shfl_xor_sync(0xffffffffu, mm[h], off);
                float os = __shfl_xor_sync(0xffffffffu, s[h], off);
                float nm = fmaxf(mm[h], om);
                float t = (s[h] > 0.f ? s[h] * __expf(mm[h] - nm) : 0.f)
                        + (os > 0.f ? os * __expf(om - nm) : 0.f);
                mm[h] = nm; s[h] = t;
            }
        }
#pragma unroll
        for (int h = 0; h < 4; h++) { m[h] = mm[h]; inv[h] = 1.f / (s[h] + 1e-16f); }
    }

    float4 acc[4];
#pragma unroll
    for (int h = 0; h < 4; h++) acc[h] = make_float4(0.f, 0.f, 0.f, 0.f);
    float acce[4] = {0.f, 0.f, 0.f, 0.f};

    for (int base = start; base < end; base += 32) {
        int cnt = min(32, end - base);
        if (deg > 32) {
            int e2 = base + lane;
            __syncwarp();
            if (e2 < end) {
                float4 lgv = *(const float4*)(g_lg + (size_t)e2 * 4);
                swp[lane * 4 + 0] = __expf(lgv.x - m[0]) * inv[0];
                swp[lane * 4 + 1] = __expf(lgv.y - m[1]) * inv[1];
                swp[lane * 4 + 2] = __expf(lgv.z - m[2]) * inv[2];
                swp[lane * 4 + 3] = __expf(lgv.w - m[3]) * inv[3];
                scp[lane] = col[e2];
            }
        }
        __syncwarp();
#pragma unroll 4
        for (int j = 0; j < cnt; j++) {
            int cj = scp[j];
            float4 wv = *(const float4*)(swp + j * 4);
            float4 xv = *(const float4*)(x + (size_t)cj * 128 + lane * 4);
            acc[0].x += wv.x * xv.x; acc[0].y += wv.x * xv.y; acc[0].z += wv.x * xv.z; acc[0].w += wv.x * xv.w;
            acc[1].x += wv.y * xv.x; acc[1].y += wv.y * xv.y; acc[1].z += wv.y * xv.z; acc[1].w += wv.y * xv.w;
            acc[2].x += wv.z * xv.x; acc[2].y += wv.z * xv.y; acc[2].z += wv.z * xv.z; acc[2].w += wv.z * xv.w;
            acc[3].x += wv.w * xv.x; acc[3].y += wv.w * xv.y; acc[3].z += wv.w * xv.z; acc[3].w += wv.w * xv.w;
            if (lane < 16) {
                float eav = ea[(size_t)(base + j) * 16 + lane];
                acce[0] += wv.x * eav; acce[1] += wv.y * eav;
                acce[2] += wv.z * eav; acce[3] += wv.w * eav;
            }
        }
    }
    // epilogue: write xobj / xe as bf16 hi/lo
#pragma unroll
    for (int h = 0; h < 4; h++) {
        uint32_t h01, h23, l01, l23;
        split4(acc[h], h01, h23, l01, l23);
        size_t off = ((size_t)nd * 4 + h) * 128 + lane * 4;
        *(uint2*)(g_obhi + off) = make_uint2(h01, h23);
        *(uint2*)(g_oblo + off) = make_uint2(l01, l23);
    }
    if (lane < 16) {
#pragma unroll
        for (int h = 0; h < 4; h++) {
            float v = acce[h];
            uint32_t b = __float_as_uint(v);
            size_t off = ((size_t)nd * 4 + h) * 16 + lane;
            g_xehi[off] = __ushort_as_bfloat16((unsigned short)(b >> 16));
            g_xelo[off] = __float2bfloat16(v - __uint_as_float(b & 0xffff0000u));
        }
    }
}

// ---------------- K3: MLP layer 1 via mma.sync, streamed buffers --------------
// smem: A[128][280] bf16 (71680 B) + B[64][280] bf16 (35840 B) = 107520 -> 2 CTA/SM
#define SA1 280
#define SMB1 71680
#define MLP1_SMEM 107520
__global__ void __launch_bounds__(256, 2) k_mlp1h(const float* __restrict__ b1, int n) {
    extern __shared__ char smem[];
    uint32_t sb = smem_u32(smem);
    int tid = threadIdx.x, lane = tid & 31, wid = tid >> 5;
    int h = blockIdx.y;
    int n0 = blockIdx.x * 128;

    float c4[2][4][4] = {};
    int wm = wid & 3, wn = wid >> 2;
    uint32_t aB = sb + wm * 32 * (SA1 * 2);
    uint32_t bB = sb + SMB1 + wn * 32 * (SA1 * 2);

    // ---- fill A (hi) + B (hi) ----
    {
        for (int i = tid; i < 128 * 34; i += 256) {
            int r = i / 34, c = i - r * 34;
            int nd = n0 + r;
            uint32_t dst = sb + r * 560 + c * 16;
            if (nd < n) {
                const char* src;
                if (c < 16)      src = (const char*)(g_xhi + (size_t)nd * 128) + c * 16;
                else if (c < 32) src = (const char*)(g_obhi + ((size_t)nd * 4 + h) * 128) + (c - 16) * 16;
                else             src = (const char*)(g_xehi + ((size_t)nd * 4 + h) * 16) + (c - 32) * 16;
                cpa16(dst, src);
            } else {
                *(uint4*)(smem + r * 560 + c * 16) = make_uint4(0, 0, 0, 0);
            }
        }
        const __nv_bfloat16* ws = g_w1s + (size_t)(h * 2 + 0) * OUT_H * F_MLP;
        for (int i = tid; i < 64 * 34; i += 256) {
            int r = i / 34, c = i - r * 34;
            cpa16(sb + SMB1 + r * 560 + c * 16, (const char*)(ws + (size_t)r * F_MLP) + c * 16);
        }
        CPWAIT();
        __syncthreads();
    }
    mma_block<17, SA1, SA1>(c4, aB, bB, lane);      // A_hi * B_hi
    __syncthreads();
    // ---- refill B (lo) ----
    {
        const __nv_bfloat16* ws = g_w1s + (size_t)(h * 2 + 1) * OUT_H * F_MLP;
        for (int i = tid; i < 64 * 34; i += 256) {
            int r = i / 34, c = i - r * 34;
            cpa16(sb + SMB1 + r * 560 + c * 16, (const char*)(ws + (size_t)r * F_MLP) + c * 16);
        }
        CPWAIT();
        __syncthreads();
    }
    mma_block<17, SA1, SA1>(c4, aB, bB, lane);      // A_hi * B_lo
    __syncthreads();
    // ---- refill A (lo) + B (hi) ----
    {
        for (int i = tid; i < 128 * 34; i += 256) {
            int r = i / 34, c = i - r * 34;
            int nd = n0 + r;
            uint32_t dst = sb + r * 560 + c * 16;
            if (nd < n) {
                const char* src;
                if (c < 16)      src = (const char*)(g_xlo + (size_t)nd * 128) + c * 16;
                else if (c < 32) src = (const char*)(g_oblo + ((size_t)nd * 4 + h) * 128) + (c - 16) * 16;
                else             src = (const char*)(g_xelo + ((size_t)nd * 4 + h) * 16) + (c - 32) * 16;
                cpa16(dst, src);
            } else {
                *(uint4*)(smem + r * 560 + c * 16) = make_uint4(0, 0, 0, 0);
            }
        }
        const __nv_bfloat16* ws = g_w1s + (size_t)(h * 2 + 0) * OUT_H * F_MLP;
        for (int i = tid; i < 64 * 34; i += 256) {
            int r = i / 34, c = i - r * 34;
            cpa16(sb + SMB1 + r * 560 + c * 16, (const char*)(ws + (size_t)r * F_MLP) + c * 16);
        }
        CPWAIT();
        __syncthreads();
    }
    mma_block<17, SA1, SA1>(c4, aB, bB, lane);      // A_lo * B_hi

    // epilogue: bias + ReLU -> g_h1
    const float* bb = b1 + h * 64;
    int g = lane >> 2, tc2 = 2 * (lane & 3);
#pragma unroll
    for (int mi = 0; mi < 2; mi++) {
#pragma unroll
        for (int ni = 0; ni < 4; ni++) {
            int colo = wn * 32 + ni * 8 + tc2;
            float2 bv = *(const float2*)(bb + colo);
            int ndr = n0 + wm * 32 + mi * 16 + g;
            float* dst = g_h1 + (size_t)ndr * 256 + h * 64 + colo;
            if (ndr < n) {
                *(float2*)dst = make_float2(fmaxf(c4[mi][ni][0] + bv.x, 0.f),
                                            fmaxf(c4[mi][ni][1] + bv.y, 0.f));
            }
            if (ndr + 8 < n) {
                *(float2*)(dst + 8 * 256) = make_float2(fmaxf(c4[mi][ni][2] + bv.x, 0.f),
                                                        fmaxf(c4[mi][ni][3] + bv.y, 0.f));
            }
        }
    }
}

// ---------------- K3b: BN partial sums over g_h1 ------------------------------
__global__ void k_bnsum(int n) {
    int t = threadIdx.x;   // 256 -> (h,o)
    float s = 0.f, q = 0.f;
    for (int nd = blockIdx.x; nd < n; nd += gridDim.x) {
        float v = g_h1[(size_t)nd * 256 + t];
        s += v; q += v * v;
    }
    atomicAdd(&g_sum[t], s);
    atomicAdd(&g_sqsum[t], q);
}

// ---------------- K4: finalize BN stats ---------------------------------------
__global__ void k_stats(const float* __restrict__ gamma, const float* __restrict__ beta, int n) {
    int i = threadIdx.x;   // 256
    float inv_n = 1.f / (float)n;
    float mu = g_sum[i] * inv_n;
    float var = g_sqsum[i] * inv_n - mu * mu;
    float r = rsqrtf(var + 1e-5f);
    float a = r * gamma[i];
    g_a[i] = a;
    g_c[i] = beta[i] - mu * a;
}

// ---------------- K5: BN apply + MLP layer 2 via mma.sync ---------------------
#define SA2 72
#define A2HI 0
#define A2LO (128 * SA2 * 2)                 // 18432
#define B2HI (2 * 128 * SA2 * 2)             // 36864
#define B2LO (B2HI + 64 * SA2 * 2)           // 46080
#define MLP2_SMEM (B2LO + 64 * SA2 * 2)      // 55296
__global__ void __launch_bounds__(256) k_mlp2h(const float* __restrict__ b2,
                                               float* __restrict__ out, int n) {
    extern __shared__ char smem[];
    uint32_t sb = smem_u32(smem);
    int tid = threadIdx.x, lane = tid & 31, wid = tid >> 5;
    int h = blockIdx.y;
    int n0 = blockIdx.x * 128;

    // fill B hi/lo via cp.async from pre-split w2
    {
        const char* wh = (const char*)(g_w2s + (size_t)(h * 2 + 0) * OUT_H * 64);
        const char* wl = (const char*)(g_w2s + (size_t)(h * 2 + 1) * OUT_H * 64);
        for (int i = tid; i < 64 * 8; i += 256) {
            int r = i >> 3, c = i & 7;
            cpa16(sb + B2HI + r * 144 + c * 16, wh + (size_t)r * 128 + c * 16);
            cpa16(sb + B2LO + r * 144 + c * 16, wl + (size_t)r * 128 + c * 16);
        }
    }
    // fill A: BN-applied h1 (inline split; K=64 only)
    for (int i = tid; i < 128 * 16; i += 256) {
        int nl = i >> 4, f = (i & 15) * 4;
        int nd = n0 + nl;
        float4 v = make_float4(0.f, 0.f, 0.f, 0.f);
        if (nd < n) {
            float4 hv = *(const float4*)(g_h1 + (size_t)nd * 256 + h * 64 + f);
            float4 av = *(const float4*)(g_a + h * 64 + f);
            float4 cv = *(const float4*)(g_c + h * 64 + f);
            v = make_float4(hv.x * av.x + cv.x, hv.y * av.y + cv.y,
                            hv.z * av.z + cv.z, hv.w * av.w + cv.w);
        }
        uint32_t h01, h23, l01, l23;
        split4(v, h01, h23, l01, l23);
        *(uint2*)(smem + A2HI + (nl * SA2 + f) * 2) = make_uint2(h01, h23);
        *(uint2*)(smem + A2LO + (nl * SA2 + f) * 2) = make_uint2(l01, l23);
    }
    CPWAIT();
    __syncthreads();

    float c4[2][4][4] = {};
    int wm = wid & 3, wn = wid >> 2;
    uint32_t aH = sb + A2HI + wm * 32 * SA2 * 2;
    uint32_t aL = sb + A2LO + wm * 32 * SA2 * 2;
    uint32_t bH = sb + B2HI + wn * 32 * SA2 * 2;
    uint32_t bL = sb + B2LO + wn * 32 * SA2 * 2;
    mma_block<4, SA2, SA2>(c4, aH, bH, lane);
    mma_block<4, SA2, SA2>(c4, aH, bL, lane);
    mma_block<4, SA2, SA2>(c4, aL, bH, lane);

    // epilogue: bias -> out
    const float* bb = b2 + h * 64;
    int g = lane >> 2, tc2 = 2 * (lane & 3);
#pragma unroll
    for (int mi = 0; mi < 2; mi++) {
#pragma unroll
        for (int ni = 0; ni < 4; ni++) {
            int colo = wn * 32 + ni * 8 + tc2;
            float2 bv = *(const float2*)(bb + colo);
            int ndr = n0 + wm * 32 + mi * 16 + g;
            float* dst = out + (size_t)ndr * 256 + h * 64 + colo;
            if (ndr < n)
                *(float2*)dst = make_float2(c4[mi][ni][0] + bv.x, c4[mi][ni][1] + bv.y);
            if (ndr + 8 < n)
                *(float2*)(dst + 8 * 256) =
                    make_float2(c4[mi][ni][2] + bv.x, c4[mi][ni][3] + bv.y);
        }
    }
}

// ---------------- launch ------------------------------------------------------
extern "C" void kernel_launch(void* const* d_in, const int* in_sizes, int n_in,
                              void* d_out, int out_size) {
    const float* x     = (const float*)d_in[0];
    const int*   row   = (const int*)d_in[1];
    const int*   col   = (const int*)d_in[2];
    const float* ea    = (const float*)d_in[3];
    const float* a1w   = (const float*)d_in[4];
    const float* a2w   = (const float*)d_in[5];
    const float* aew   = (const float*)d_in[6];
    const float* w1    = (const float*)d_in[7];
    const float* b1    = (const float*)d_in[8];
    const float* gamma = (const float*)d_in[9];
    const float* beta  = (const float*)d_in[10];
    const float* w2    = (const float*)d_in[11];
    const float* b2    = (const float*)d_in[12];
    float* out = (float*)d_out;

    int n = in_sizes[0] / IN_DIM;
    int e = in_sizes[1];

    cudaFuncSetAttribute(k_mlp1h, cudaFuncAttributeMaxDynamicSharedMemorySize, MLP1_SMEM);
    cudaFuncSetAttribute(k_mlp2h, cudaFuncAttributeMaxDynamicSharedMemorySize, MLP2_SMEM);

    k_rowptr<<<(n + 256) / 256, 256>>>(row, n, e);
    k_nodelogits<<<(n + 7) / 8, 256>>>(x, a1w, a2w, n);
    k_pre<<<4, 256>>>(w1, w2);
    k_xsplit<<<(n * 32 + 255) / 256, 256>>>(x, n);
    k_edge<<<(n + 7) / 8, 256>>>(x, col, ea, aew, n);
    dim3 g3((n + 127) / 128, 4);
    k_mlp1h<<<g3, 256, MLP1_SMEM>>>(b1, n);
    k_bnsum<<<296, 256>>>(n);
    k_stats<<<1, 256>>>(gamma, beta, n);
    k_mlp2h<<<g3, 256, MLP2_SMEM>>>(b2, out, n);
}